// round 12
// baseline (speedup 1.0000x reference)
#include <cuda_runtime.h>

typedef unsigned long long u64;
typedef unsigned int u32;

#define BATCH 16
#define IMG_H 512
#define IMG_W 512
#define NPIX (IMG_H * IMG_W)      // 262144
#define WPR 8                     // 64-bit words per row
#define WPI (NPIX / 64)           // 4096 words per image
#define BLOCK 1024
#define MAXRUNS 16384             // runs per image bound (blobby masks ~<=8k)

// Dynamic smem layout (bytes):
//   A      : WPI u64      = 32768
//   B      : WPI u64      = 32768
//   parent : MAXRUNS int  = 65536
//   csize  : MAXRUNS int  = 65536
//   prevcnt: WPI int      = 16384
//   sa,sb  : 512 int each = 4096
//   rowb   : 512 int      = 2048
//   misc   : 16 int       = 64
#define SMEM_BYTES (2 * WPI * 8 + 2 * MAXRUNS * 4 + WPI * 4 + 3 * IMG_H * 4 + 64)

// ---------------------------------------------------------------------------
// SE half-widths (compile-time)
// ---------------------------------------------------------------------------
template <int R>
__device__ __forceinline__ constexpr int hw_disk(int dy) {
    int best = 0;
    for (int x = 0; x <= R; x++)
        if (x * x + dy * dy <= R * R) best = x;
    return best;
}
// disk(2) (+) disk(5) Minkowski sum
__device__ __forceinline__ constexpr int hw_comb(int dy) {
    int best = -1;
    for (int a = -5; a <= 5; a++) {
        int b = dy - a;
        if (b < -2 || b > 2) continue;
        int h5 = 0, h2 = 0;
        for (int x = 0; x <= 5; x++) if (x * x + a * a <= 25) h5 = x;
        for (int x = 0; x <= 2; x++) if (x * x + b * b <= 4)  h2 = x;
        if (h5 + h2 > best) best = h5 + h2;
    }
    return best;
}
__device__ __forceinline__ constexpr int row_order(int i) {
    return (i & 1) ? -((i + 1) / 2) : (i / 2);   // 0,-1,1,-2,2,...
}

// ---------------------------------------------------------------------------
// smem union-find
// ---------------------------------------------------------------------------
__device__ __forceinline__ int uf_find(int* parent, int i) {
    int p = parent[i];
    while (p != i) { i = p; p = parent[i]; }
    return i;
}
__device__ void uf_merge(int* parent, int a, int b) {
    while (true) {
        a = uf_find(parent, a);
        b = uf_find(parent, b);
        if (a == b) return;
        int lo = a < b ? a : b;
        int hi = a < b ? b : a;
        int old = atomicMin(&parent[hi], lo);
        if (old == hi) return;
        a = lo; b = old;
    }
}

// segment helpers
__device__ __forceinline__ int seg_len(u64 rem, int j) {
    u64 inv = ~(rem >> j);
    return inv ? (__ffsll((long long)inv) - 1) : (64 - j);
}
__device__ __forceinline__ u64 seg_bits(int j, int len) {
    return (j + len >= 64) ? (~0ull << j) : (((1ull << len) - 1ull) << j);
}

// ---------------------------------------------------------------------------
// CCL + filter: src (smem) -> dst (smem). MODE 0: keep-big. 1: ~keep-big.
// 2: hole fill (src is bg; dst = ~bg | small-bg-comp).
// ---------------------------------------------------------------------------
template <int MODE>
__device__ void ccl_filter(const u64* __restrict__ M, u64* __restrict__ D,
                           int* parent, int* csize, int* prevcnt,
                           int* sa, int* sb, int* rowb, int* misc,
                           int min_size, bool guard) {
    int tid = threadIdx.x;

    // (a) runs per row
    for (int r = tid; r < IMG_H; r += BLOCK) {
        int cnt = 0; u64 prevtop = 0;
        for (int w = 0; w < WPR; w++) {
            u64 m = M[r * WPR + w];
            cnt += __popcll(m & ~((m << 1) | prevtop));
            prevtop = m >> 63;
        }
        sa[r] = cnt;
    }
    __syncthreads();

    // (b) inclusive scan (Hillis-Steele, ping-pong)
    int* cur = sa; int* nxt = sb;
    for (int d = 1; d < IMG_H; d <<= 1) {
        for (int r = tid; r < IMG_H; r += BLOCK)
            nxt[r] = cur[r] + ((r >= d) ? cur[r - d] : 0);
        __syncthreads();
        int* t = cur; cur = nxt; nxt = t;
    }
    for (int r = tid; r < IMG_H; r += BLOCK)
        rowb[r] = r ? cur[r - 1] : 0;
    if (tid == 0) { misc[0] = 0; misc[1] = cur[IMG_H - 1]; }
    __syncthreads();

    // (c) run-id assignment: prevcnt per word, parent/csize per run
    for (int r = tid; r < IMG_H; r += BLOCK) {
        int base = rowb[r];
        int cnt = 0, curlen = 0;
        bool open = false;
        u64 prevtop = 0;
        for (int w = 0; w < WPR; w++) {
            int g = r * WPR + w;
            prevcnt[g] = base + cnt;
            u64 m = M[g];
            u64 rem = m;
            while (rem) {
                int j = __ffsll((long long)rem) - 1;
                int len = seg_len(rem, j);
                if (j == 0 && open && prevtop) {
                    curlen += len;          // continuation across word boundary
                } else {
                    if (open) { int id = base + cnt - 1; parent[id] = id; csize[id] = curlen; }
                    open = true; cnt++; curlen = len;
                }
                u64 sb_ = seg_bits(j, len);
                rem &= ~sb_;
            }
            prevtop = m >> 63;
        }
        if (open) { int id = base + cnt - 1; parent[id] = id; csize[id] = curlen; }
    }
    __syncthreads();

    // (d) vertical merges per word
    for (int g = tid; g < WPI; g += BLOCK) {
        int r = g >> 3;
        if (r == 0) continue;
        u64 cm = M[g], um = M[g - WPR];
        u64 both = cm & um;
        if (!both) continue;
        int wx = g & 7;
        u64 ptc = wx ? (M[g - 1] >> 63) : 0;
        u64 ptu = wx ? (M[g - WPR - 1] >> 63) : 0;
        u64 stc = cm & ~((cm << 1) | ptc);
        u64 stu = um & ~((um << 1) | ptu);
        int bc = prevcnt[g], bu = prevcnt[g - WPR];
        u64 rem = both;
        while (rem) {
            int j = __ffsll((long long)rem) - 1;
            int len = seg_len(rem, j);
            u64 below = (j == 63) ? ~0ull : ((2ull << j) - 1ull);
            int idc = bc + __popcll(stc & below) - 1;
            int idu = bu + __popcll(stu & below) - 1;
            uf_merge(parent, idc, idu);
            rem &= ~seg_bits(j, len);
        }
    }
    __syncthreads();

    // (e) finalize per run: compress, accumulate sizes, count roots
    int total = misc[1];
    for (int id = tid; id < total; id += BLOCK) {
        int root = uf_find(parent, id);
        if (root != id) {
            parent[id] = root;
            atomicAdd(&csize[root], csize[id]);
        } else {
            atomicAdd(&misc[0], 1);
        }
    }
    __syncthreads();

    // (f) filter per word -> D
    bool keepall = (MODE != 2) && guard && (misc[0] <= 1);
    for (int g = tid; g < WPI; g += BLOCK) {
        u64 m = M[g];
        u64 out = (MODE == 2) ? ~m : 0ull;
        if (m) {
            int wx = g & 7;
            u64 pt = wx ? (M[g - 1] >> 63) : 0;
            u64 st = m & ~((m << 1) | pt);
            int base = prevcnt[g];
            u64 rem = m;
            while (rem) {
                int j = __ffsll((long long)rem) - 1;
                int len = seg_len(rem, j);
                u64 below = (j == 63) ? ~0ull : ((2ull << j) - 1ull);
                int id = base + __popcll(st & below) - 1;
                int sz = csize[parent[id]];
                u64 bits = seg_bits(j, len);
                if (MODE == 2) {
                    if (sz < min_size) out |= bits;
                } else {
                    if (keepall || sz >= min_size) out |= bits;
                }
                rem &= ~bits;
            }
        }
        D[g] = (MODE == 1) ? ~out : out;
    }
    __syncthreads();
}

// ---------------------------------------------------------------------------
// smem morphology. Erode OOB=1, dilate OOB=0.
// ---------------------------------------------------------------------------
template <int R, bool COMB>
__device__ void sm_erode(const u64* __restrict__ in, u64* __restrict__ dst) {
    int tid = threadIdx.x;
    const int NR = 2 * R + 1;
    for (int wg = tid; wg < WPI; wg += BLOCK) {
        int w = wg & (WPR - 1);
        int y = wg >> 3;
        u64 acc = ~0ull;
#pragma unroll
        for (int i = 0; i < NR; i++) {
            const int dy = row_order(i);
            int yy = y + dy;
            if (yy < 0 || yy >= IMG_H) continue;
            int rw = wg + dy * WPR;
            u64 mid = in[rw];
            u64 lo = (w == 0) ? ~0ull : in[rw - 1];
            u64 hi = (w == WPR - 1) ? ~0ull : in[rw + 1];
            u64 a = mid;
            const int h = COMB ? hw_comb(dy) : hw_disk<R>(dy);
#pragma unroll
            for (int k = 1; k <= h; k++) {
                a &= (mid >> k) | (hi << (64 - k));
                a &= (mid << k) | (lo >> (64 - k));
            }
            acc &= a;
            if (!acc) break;
        }
        dst[wg] = acc;
    }
    __syncthreads();
}

template <int R>
__device__ void sm_dilate(const u64* __restrict__ in, u64* __restrict__ dst) {
    int tid = threadIdx.x;
    const int NR = 2 * R + 1;
    for (int wg = tid; wg < WPI; wg += BLOCK) {
        int w = wg & (WPR - 1);
        int y = wg >> 3;
        u64 acc = 0ull;
#pragma unroll
        for (int i = 0; i < NR; i++) {
            const int dy = row_order(i);
            int yy = y + dy;
            if (yy < 0 || yy >= IMG_H) continue;
            int rw = wg + dy * WPR;
            u64 mid = in[rw];
            u64 lo = (w == 0) ? 0ull : in[rw - 1];
            u64 hi = (w == WPR - 1) ? 0ull : in[rw + 1];
            u64 a = mid;
            const int h = hw_disk<R>(dy);
#pragma unroll
            for (int k = 1; k <= h; k++) {
                a |= (mid >> k) | (hi << (64 - k));
                a |= (mid << k) | (lo >> (64 - k));
            }
            acc |= a;
            if (acc == ~0ull) break;
        }
        dst[wg] = acc;
    }
    __syncthreads();
}

// dilate disk(1) fused with float unpack; warp per word, coalesced stores
__device__ void sm_dilate1_out(const u64* __restrict__ in, float* __restrict__ out) {
    int warp = threadIdx.x >> 5;
    int lane = threadIdx.x & 31;
    for (int wg = warp; wg < WPI; wg += (BLOCK / 32)) {
        int w = wg & (WPR - 1);
        int y = wg >> 3;
        u64 mid = in[wg];
        u64 lo = (w == 0) ? 0ull : in[wg - 1];
        u64 hi = (w == WPR - 1) ? 0ull : in[wg + 1];
        u64 a = mid | ((mid >> 1) | (hi << 63)) | ((mid << 1) | (lo >> 63));
        if (y > 0)          a |= in[wg - WPR];
        if (y < IMG_H - 1)  a |= in[wg + WPR];
        int base = wg * 64;
        out[base + lane]      = ((a >> lane) & 1ull) ? 1.0f : 0.0f;
        out[base + 32 + lane] = ((a >> (lane + 32)) & 1ull) ? 1.0f : 0.0f;
    }
}

// ---------------------------------------------------------------------------
// One CTA per image; whole pipeline in shared memory
// ---------------------------------------------------------------------------
__global__ void __launch_bounds__(BLOCK, 1)
k_pipeline(const float* __restrict__ in, float* __restrict__ out) {
    extern __shared__ char smraw[];
    u64* A       = (u64*)smraw;
    u64* B       = A + WPI;
    int* parent  = (int*)(B + WPI);
    int* csize   = parent + MAXRUNS;
    int* prevcnt = csize + MAXRUNS;
    int* sa      = prevcnt + WPI;
    int* sb      = sa + IMG_H;
    int* rowb    = sb + IMG_H;
    int* misc    = rowb + IMG_H;

    int img = blockIdx.x;
    int tid = threadIdx.x;
    const float* src = in + (long long)img * NPIX;
    float* dst = out + (long long)img * NPIX;

    // binarize -> A
    for (int p = tid; p < NPIX; p += BLOCK) {
        unsigned b = __ballot_sync(0xffffffffu, src[p] > 0.0f);
        if ((tid & 31) == 0) ((u32*)A)[p >> 5] = b;
    }
    __syncthreads();

    // remove_small_objects(A, 2000, guard); output inverted (bg) -> B
    ccl_filter<1>(A, B, parent, csize, prevcnt, sa, sb, rowb, misc, 2000, true);

    // hole fill on bg (B) -> A
    ccl_filter<2>(B, A, parent, csize, prevcnt, sa, sb, rowb, misc, 301, false);

    // erode disk2 then disk5 (fused Minkowski sum): A -> B
    sm_erode<7, true>(A, B);
    // opening dilate disk5: B -> A
    sm_dilate<5>(B, A);

    // remove_small_objects(A, 2000, guard) -> B
    ccl_filter<0>(A, B, parent, csize, prevcnt, sa, sb, rowb, misc, 2000, true);

    // dilate disk1 + float unpack -> gmem
    sm_dilate1_out(B, dst);
}

extern "C" void kernel_launch(void* const* d_in, const int* in_sizes, int n_in,
                              void* d_out, int out_size) {
    const float* in = (const float*)d_in[0];
    float* out = (float*)d_out;
    cudaFuncSetAttribute(k_pipeline, cudaFuncAttributeMaxDynamicSharedMemorySize,
                         SMEM_BYTES);
    k_pipeline<<<BATCH, BLOCK, SMEM_BYTES>>>(in, out);
}